// round 1
// baseline (speedup 1.0000x reference)
#include <cuda_runtime.h>
#include <cuda_bf16.h>
#include <math.h>

// Problem constants
#define B_  4
#define S_  2048
#define D_  1024
#define H_  16
#define DH_ 64
#define M_  (B_ * S_)          // 8192 rows of x

// Scratch for projected Q, K, V in [B, H, S, Dh] layout
__device__ float g_Q[B_ * H_ * S_ * DH_];
__device__ float g_K[B_ * H_ * S_ * DH_];
__device__ float g_V[B_ * H_ * S_ * DH_];

// ---------------------------------------------------------------------------
// Kernel 1: fused QKV projection GEMM.
//   C = x @ W + b   for W in {Wq, Wk, Wv} selected by blockIdx.z
//   Result scattered into [B, H, S, Dh] layout.
// Tiling: BM=128, BN=128, BK=8, 256 threads, 8x8 micro-tile per thread.
// ---------------------------------------------------------------------------
__global__ __launch_bounds__(256, 2)
void qkv_gemm_kernel(const float* __restrict__ X,
                     const float* __restrict__ Wq, const float* __restrict__ bq,
                     const float* __restrict__ Wk, const float* __restrict__ bk,
                     const float* __restrict__ Wv, const float* __restrict__ bv)
{
    __shared__ float As[8 * 128];   // transposed: As[k][m]
    __shared__ float Bs[8 * 128];   // Bs[k][n]

    const int tid = threadIdx.x;
    const int m0 = blockIdx.y * 128;
    const int n0 = blockIdx.x * 128;
    const int z  = blockIdx.z;

    const float* W    = (z == 0) ? Wq : (z == 1) ? Wk : Wv;
    const float* bias = (z == 0) ? bq : (z == 1) ? bk : bv;
    float* dst        = (z == 0) ? g_Q : (z == 1) ? g_K : g_V;

    const int ty = tid >> 4;        // 0..15
    const int tx = tid & 15;        // 0..15

    // A load indices: 128 rows x 8 cols, one float4 per thread
    const int a_row = tid >> 1;           // 0..127
    const int a_c4  = (tid & 1) << 2;     // 0 or 4
    // B load indices: 8 rows x 128 cols, one float4 per thread
    const int b_row = tid >> 5;           // 0..7
    const int b_c4  = (tid & 31) << 2;    // 0..124

    float acc[8][8];
    #pragma unroll
    for (int i = 0; i < 8; i++)
        #pragma unroll
        for (int j = 0; j < 8; j++) acc[i][j] = 0.0f;

    for (int kt = 0; kt < D_; kt += 8) {
        // Load A tile (transpose into smem)
        float4 av = *reinterpret_cast<const float4*>(
            &X[(size_t)(m0 + a_row) * D_ + kt + a_c4]);
        As[(a_c4 + 0) * 128 + a_row] = av.x;
        As[(a_c4 + 1) * 128 + a_row] = av.y;
        As[(a_c4 + 2) * 128 + a_row] = av.z;
        As[(a_c4 + 3) * 128 + a_row] = av.w;
        // Load B tile
        float4 bv4 = *reinterpret_cast<const float4*>(
            &W[(size_t)(kt + b_row) * D_ + n0 + b_c4]);
        *reinterpret_cast<float4*>(&Bs[b_row * 128 + b_c4]) = bv4;
        __syncthreads();

        #pragma unroll
        for (int k = 0; k < 8; k++) {
            float a[8], bb[8];
            float4 a0 = *reinterpret_cast<const float4*>(&As[k * 128 + ty * 8]);
            float4 a1 = *reinterpret_cast<const float4*>(&As[k * 128 + ty * 8 + 4]);
            float4 b0 = *reinterpret_cast<const float4*>(&Bs[k * 128 + tx * 8]);
            float4 b1 = *reinterpret_cast<const float4*>(&Bs[k * 128 + tx * 8 + 4]);
            a[0]=a0.x; a[1]=a0.y; a[2]=a0.z; a[3]=a0.w;
            a[4]=a1.x; a[5]=a1.y; a[6]=a1.z; a[7]=a1.w;
            bb[0]=b0.x; bb[1]=b0.y; bb[2]=b0.z; bb[3]=b0.w;
            bb[4]=b1.x; bb[5]=b1.y; bb[6]=b1.z; bb[7]=b1.w;
            #pragma unroll
            for (int i = 0; i < 8; i++)
                #pragma unroll
                for (int j = 0; j < 8; j++)
                    acc[i][j] = fmaf(a[i], bb[j], acc[i][j]);
        }
        __syncthreads();
    }

    // Bias add + scatter into [B, H, S, Dh]
    #pragma unroll
    for (int i = 0; i < 8; i++) {
        const int m = m0 + ty * 8 + i;
        const int bb_ = m >> 11;          // batch (m / 2048)
        const int s   = m & 2047;
        #pragma unroll
        for (int j = 0; j < 8; j++) {
            const int n = n0 + tx * 8 + j;
            const int h = n >> 6;
            const int d = n & 63;
            const float val = acc[i][j] + bias[n];
            dst[(((size_t)(bb_ * H_ + h)) * S_ + s) * DH_ + d] = val;
        }
    }
}

// ---------------------------------------------------------------------------
// Kernel 2: flash attention.
//   One block per (batch, head, 64-row Q tile). Streams K/V in 64-row tiles
//   with online softmax. 256 threads, 4x4 micro-tiles for both matmuls.
// Dynamic smem layout (floats):
//   Qs[64*64] | Ks[64*65] | Vs[64*65] | Ss[64*65] | row_m[64] | row_l[64] | row_c[64]
// ---------------------------------------------------------------------------
#define ATTN_SMEM_FLOATS (64*64 + 3*64*65 + 3*64)

__global__ __launch_bounds__(256, 3)
void attn_kernel(float* __restrict__ out)
{
    extern __shared__ float sm[];
    float* Qs    = sm;                    // stride 64
    float* Ks    = Qs + 64 * 64;          // stride 65
    float* Vs    = Ks + 64 * 65;          // stride 65
    float* Ss    = Vs + 64 * 65;          // stride 65
    float* row_m = Ss + 64 * 65;
    float* row_l = row_m + 64;
    float* row_c = row_l + 64;

    const int tid = threadIdx.x;
    const int qt  = blockIdx.x;   // 0..31
    const int h   = blockIdx.y;   // 0..15
    const int b   = blockIdx.z;   // 0..3

    const size_t head_base = ((size_t)(b * H_ + h)) * S_ * DH_;
    const float* Qg = g_Q + head_base + (size_t)qt * 64 * DH_;
    const float* Kg = g_K + head_base;
    const float* Vg = g_V + head_base;

    // Load Q tile (64x64) as float4
    #pragma unroll
    for (int it = 0; it < 4; it++) {
        const int idx = it * 256 + tid;            // 0..1023 float4s
        const int r = idx >> 4;
        const int c = (idx & 15) << 2;
        *reinterpret_cast<float4*>(&Qs[r * 64 + c]) =
            *reinterpret_cast<const float4*>(&Qg[r * DH_ + c]);
    }
    if (tid < 64) { row_m[tid] = -INFINITY; row_l[tid] = 0.0f; }

    const int ty = tid >> 4;    // 0..15
    const int tx = tid & 15;    // 0..15
    const float scale = 0.125f; // 1/sqrt(64)

    float acc[4][4];
    #pragma unroll
    for (int i = 0; i < 4; i++)
        #pragma unroll
        for (int j = 0; j < 4; j++) acc[i][j] = 0.0f;

    for (int kt = 0; kt < S_ / 64; kt++) {
        __syncthreads();   // previous iteration done with Ks/Vs/Ss (also covers Q load)
        // Load K and V tiles (64x64 each), padded stride 65
        #pragma unroll
        for (int it = 0; it < 4; it++) {
            const int idx = it * 256 + tid;
            const int r = idx >> 4;
            const int c = (idx & 15) << 2;
            float4 kv = *reinterpret_cast<const float4*>(&Kg[(size_t)(kt * 64 + r) * DH_ + c]);
            Ks[r * 65 + c + 0] = kv.x; Ks[r * 65 + c + 1] = kv.y;
            Ks[r * 65 + c + 2] = kv.z; Ks[r * 65 + c + 3] = kv.w;
            float4 vv = *reinterpret_cast<const float4*>(&Vg[(size_t)(kt * 64 + r) * DH_ + c]);
            Vs[r * 65 + c + 0] = vv.x; Vs[r * 65 + c + 1] = vv.y;
            Vs[r * 65 + c + 2] = vv.z; Vs[r * 65 + c + 3] = vv.w;
        }
        __syncthreads();

        // Phase 1: S = scale * Q @ K^T   (64x64)
        float sa[4][4];
        #pragma unroll
        for (int i = 0; i < 4; i++)
            #pragma unroll
            for (int j = 0; j < 4; j++) sa[i][j] = 0.0f;
        #pragma unroll 8
        for (int k = 0; k < 64; k++) {
            float a[4], bb[4];
            #pragma unroll
            for (int i = 0; i < 4; i++) a[i]  = Qs[(ty * 4 + i) * 64 + k];
            #pragma unroll
            for (int j = 0; j < 4; j++) bb[j] = Ks[(tx * 4 + j) * 65 + k];
            #pragma unroll
            for (int i = 0; i < 4; i++)
                #pragma unroll
                for (int j = 0; j < 4; j++)
                    sa[i][j] = fmaf(a[i], bb[j], sa[i][j]);
        }
        #pragma unroll
        for (int i = 0; i < 4; i++)
            #pragma unroll
            for (int j = 0; j < 4; j++)
                Ss[(ty * 4 + i) * 65 + tx * 4 + j] = sa[i][j] * scale;
        __syncthreads();

        // Phase 2: online softmax per row (threads 0..63)
        if (tid < 64) {
            const int r = tid;
            float mloc = -INFINITY;
            #pragma unroll 8
            for (int c = 0; c < 64; c++) mloc = fmaxf(mloc, Ss[r * 65 + c]);
            const float m_old = row_m[r];
            const float m_new = fmaxf(m_old, mloc);
            const float corr  = __expf(m_old - m_new);
            float sum = 0.0f;
            #pragma unroll 8
            for (int c = 0; c < 64; c++) {
                const float p = __expf(Ss[r * 65 + c] - m_new);
                Ss[r * 65 + c] = p;
                sum += p;
            }
            row_m[r] = m_new;
            row_l[r] = row_l[r] * corr + sum;
            row_c[r] = corr;
        }
        __syncthreads();

        // Phase 3: O = O*corr + P @ V
        #pragma unroll
        for (int i = 0; i < 4; i++) {
            const float cf = row_c[ty * 4 + i];
            #pragma unroll
            for (int j = 0; j < 4; j++) acc[i][j] *= cf;
        }
        #pragma unroll 8
        for (int k = 0; k < 64; k++) {
            float a[4], bb[4];
            #pragma unroll
            for (int i = 0; i < 4; i++) a[i]  = Ss[(ty * 4 + i) * 65 + k];
            #pragma unroll
            for (int j = 0; j < 4; j++) bb[j] = Vs[k * 65 + tx * 4 + j];
            #pragma unroll
            for (int i = 0; i < 4; i++)
                #pragma unroll
                for (int j = 0; j < 4; j++)
                    acc[i][j] = fmaf(a[i], bb[j], acc[i][j]);
        }
    }

    // Final normalize + store to [B, S, D] with head merge
    #pragma unroll
    for (int i = 0; i < 4; i++) {
        const int q = ty * 4 + i;
        const float inv_l = 1.0f / row_l[q];
        const size_t row_off = ((size_t)(b * S_ + qt * 64 + q)) * D_ + h * DH_;
        #pragma unroll
        for (int j = 0; j < 4; j++) {
            const int d = tx * 4 + j;
            out[row_off + d] = acc[i][j] * inv_l;
        }
    }
}

// ---------------------------------------------------------------------------
extern "C" void kernel_launch(void* const* d_in, const int* in_sizes, int n_in,
                              void* d_out, int out_size)
{
    const float* x  = (const float*)d_in[0];
    const float* Wq = (const float*)d_in[1];
    const float* bq = (const float*)d_in[2];
    const float* Wk = (const float*)d_in[3];
    const float* bk = (const float*)d_in[4];
    const float* Wv = (const float*)d_in[5];
    const float* bv = (const float*)d_in[6];
    float* out = (float*)d_out;

    // Kernel 1: QKV projections (z selects Q/K/V)
    dim3 g1(D_ / 128, M_ / 128, 3);
    qkv_gemm_kernel<<<g1, 256>>>(x, Wq, bq, Wk, bk, Wv, bv);

    // Kernel 2: flash attention
    const int smem_bytes = ATTN_SMEM_FLOATS * sizeof(float);
    cudaFuncSetAttribute(attn_kernel,
                         cudaFuncAttributeMaxDynamicSharedMemorySize, smem_bytes);
    dim3 g2(S_ / 64, H_, B_);
    attn_kernel<<<g2, 256, smem_bytes>>>(out);
}

// round 2
// speedup vs baseline: 5.2764x; 5.2764x over previous
#include <cuda_runtime.h>
#include <cuda_bf16.h>
#include <math.h>

// Problem constants
#define B_  4
#define S_  2048
#define D_  1024
#define H_  16
#define DH_ 64
#define M_  (B_ * S_)

// Scratch for projected Q, K, V in [B, H, S, Dh] layout (fp32)
__device__ float g_Q[B_ * H_ * S_ * DH_];
__device__ float g_K[B_ * H_ * S_ * DH_];
__device__ float g_V[B_ * H_ * S_ * DH_];

// ---------------------------------------------------------------------------
// Helpers: tf32 convert + m16n8k8 tf32 mma
// ---------------------------------------------------------------------------
__device__ __forceinline__ unsigned f2tf(float f) {
    unsigned u;
    asm("cvt.rna.tf32.f32 %0, %1;" : "=r"(u) : "f"(f));
    return u;
}

__device__ __forceinline__ void mma_tf32(float c[4],
                                         unsigned a0, unsigned a1, unsigned a2, unsigned a3,
                                         unsigned b0, unsigned b1) {
    asm volatile(
        "mma.sync.aligned.m16n8k8.row.col.f32.tf32.tf32.f32 "
        "{%0,%1,%2,%3}, {%4,%5,%6,%7}, {%8,%9}, {%0,%1,%2,%3};"
        : "+f"(c[0]), "+f"(c[1]), "+f"(c[2]), "+f"(c[3])
        : "r"(a0), "r"(a1), "r"(a2), "r"(a3), "r"(b0), "r"(b1));
}

// ---------------------------------------------------------------------------
// Kernel 1: QKV projection GEMM on tensor cores (tf32).
// BM=128, BN=128, BK=16; 8 warps (2x4); warp tile 64x32; m16n8k8 mma.
// A smem: [128][20] (row-major, pad->conflict-free frag loads)
// B smem: [16][136]
// ---------------------------------------------------------------------------
#define AS_STRIDE 20
#define BS_STRIDE 136

__global__ __launch_bounds__(256)
void qkv_gemm_tc(const float* __restrict__ X,
                 const float* __restrict__ Wq, const float* __restrict__ bq,
                 const float* __restrict__ Wk, const float* __restrict__ bk,
                 const float* __restrict__ Wv, const float* __restrict__ bv)
{
    __shared__ unsigned As[128 * AS_STRIDE];
    __shared__ unsigned Bs[16 * BS_STRIDE];

    const int tid  = threadIdx.x;
    const int lane = tid & 31;
    const int wrp  = tid >> 5;        // 0..7
    const int g    = lane >> 2;       // 0..7
    const int t    = lane & 3;        // 0..3
    const int wm   = wrp >> 2;        // 0..1  (m offset wm*64)
    const int wn   = wrp & 3;         // 0..3  (n offset wn*32)

    const int m0 = blockIdx.y * 128;
    const int n0 = blockIdx.x * 128;
    const int z  = blockIdx.z;

    const float* W    = (z == 0) ? Wq : (z == 1) ? Wk : Wv;
    const float* bias = (z == 0) ? bq : (z == 1) ? bk : bv;
    float* dst        = (z == 0) ? g_Q : (z == 1) ? g_K : g_V;

    float acc[4][4][4];
    #pragma unroll
    for (int i = 0; i < 4; i++)
        #pragma unroll
        for (int j = 0; j < 4; j++)
            #pragma unroll
            for (int r = 0; r < 4; r++) acc[i][j][r] = 0.0f;

    // Staging indices (2 float4 each for A and B)
    int a_row[2], a_c[2], b_row[2], b_c[2];
    #pragma unroll
    for (int it = 0; it < 2; it++) {
        const int idx = tid + it * 256;
        a_row[it] = idx >> 2;  a_c[it] = (idx & 3) << 2;
        b_row[it] = idx >> 5;  b_c[it] = (idx & 31) << 2;
    }

    float4 ra[2], rb[2];
    #pragma unroll
    for (int it = 0; it < 2; it++) {
        ra[it] = *reinterpret_cast<const float4*>(
            &X[(size_t)(m0 + a_row[it]) * D_ + a_c[it]]);
        rb[it] = *reinterpret_cast<const float4*>(
            &W[(size_t)b_row[it] * D_ + n0 + b_c[it]]);
    }

    for (int kt = 0; kt < D_ / 16; kt++) {
        // store staged tile (cvt to tf32)
        #pragma unroll
        for (int it = 0; it < 2; it++) {
            unsigned* ap = &As[a_row[it] * AS_STRIDE + a_c[it]];
            ap[0] = f2tf(ra[it].x); ap[1] = f2tf(ra[it].y);
            ap[2] = f2tf(ra[it].z); ap[3] = f2tf(ra[it].w);
            unsigned* bp = &Bs[b_row[it] * BS_STRIDE + b_c[it]];
            bp[0] = f2tf(rb[it].x); bp[1] = f2tf(rb[it].y);
            bp[2] = f2tf(rb[it].z); bp[3] = f2tf(rb[it].w);
        }
        __syncthreads();

        // prefetch next tile
        if (kt + 1 < D_ / 16) {
            const int koff = (kt + 1) * 16;
            #pragma unroll
            for (int it = 0; it < 2; it++) {
                ra[it] = *reinterpret_cast<const float4*>(
                    &X[(size_t)(m0 + a_row[it]) * D_ + koff + a_c[it]]);
                rb[it] = *reinterpret_cast<const float4*>(
                    &W[(size_t)(koff + b_row[it]) * D_ + n0 + b_c[it]]);
            }
        }

        // compute: 2 k-steps of 8
        #pragma unroll
        for (int ks = 0; ks < 16; ks += 8) {
            unsigned af[4][4];
            #pragma unroll
            for (int i = 0; i < 4; i++) {
                const int rbase = (wm * 64 + i * 16 + g) * AS_STRIDE + ks + t;
                af[i][0] = As[rbase];
                af[i][1] = As[rbase + 8 * AS_STRIDE];
                af[i][2] = As[rbase + 4];
                af[i][3] = As[rbase + 8 * AS_STRIDE + 4];
            }
            unsigned bf[4][2];
            #pragma unroll
            for (int j = 0; j < 4; j++) {
                const int bbase = (ks + t) * BS_STRIDE + wn * 32 + j * 8 + g;
                bf[j][0] = Bs[bbase];
                bf[j][1] = Bs[bbase + 4 * BS_STRIDE];
            }
            #pragma unroll
            for (int i = 0; i < 4; i++)
                #pragma unroll
                for (int j = 0; j < 4; j++)
                    mma_tf32(acc[i][j], af[i][0], af[i][1], af[i][2], af[i][3],
                             bf[j][0], bf[j][1]);
        }
        __syncthreads();
    }

    // Epilogue: bias + scatter into [B, H, S, Dh]
    #pragma unroll
    for (int i = 0; i < 4; i++) {
        const int mrow0 = m0 + wm * 64 + i * 16 + g;
        const int mrow1 = mrow0 + 8;
        #pragma unroll
        for (int j = 0; j < 4; j++) {
            const int n = n0 + wn * 32 + j * 8 + 2 * t;
            const int h = n >> 6;
            const int d = n & 63;
            const float b0v = bias[n], b1v = bias[n + 1];
            {
                const int bb = mrow0 >> 11, s = mrow0 & 2047;
                float2 v = make_float2(acc[i][j][0] + b0v, acc[i][j][1] + b1v);
                *reinterpret_cast<float2*>(
                    &dst[(((size_t)(bb * H_ + h)) * S_ + s) * DH_ + d]) = v;
            }
            {
                const int bb = mrow1 >> 11, s = mrow1 & 2047;
                float2 v = make_float2(acc[i][j][2] + b0v, acc[i][j][3] + b1v);
                *reinterpret_cast<float2*>(
                    &dst[(((size_t)(bb * H_ + h)) * S_ + s) * DH_ + d]) = v;
            }
        }
    }
}

// ---------------------------------------------------------------------------
// Kernel 2: flash attention on tensor cores (tf32).
// Block = 256 threads (8 warps), Q tile 128 rows, K/V tiles 64 rows.
// Warp w owns query rows [w*16, w*16+16). Q fragments in registers.
// smem (uint32): Ks[64][68] | Vs[64][72] | Ps[128][68]
// ---------------------------------------------------------------------------
#define KS_STRIDE 68
#define VS_STRIDE 72
#define PS_STRIDE 68
#define ATTN_SMEM_U32 (64 * KS_STRIDE + 64 * VS_STRIDE + 128 * PS_STRIDE)

__global__ __launch_bounds__(256)
void attn_tc(float* __restrict__ out)
{
    extern __shared__ unsigned sm_u[];
    unsigned* Ks = sm_u;
    unsigned* Vs = Ks + 64 * KS_STRIDE;
    unsigned* Ps = Vs + 64 * VS_STRIDE;

    const int tid  = threadIdx.x;
    const int lane = tid & 31;
    const int wrp  = tid >> 5;      // 0..7 -> rows wrp*16..+15
    const int g    = lane >> 2;
    const int t    = lane & 3;

    const int qt = blockIdx.x;      // 0..15
    const int h  = blockIdx.y;
    const int b  = blockIdx.z;

    const size_t head_base = ((size_t)(b * H_ + h)) * S_ * DH_;
    const float* Qg = g_Q + head_base + (size_t)qt * 128 * DH_;
    const float* Kg = g_K + head_base;
    const float* Vg = g_V + head_base;

    // Stage Q (128x64) into Ps, cvt tf32
    #pragma unroll
    for (int it = 0; it < 8; it++) {
        const int idx = tid + it * 256;            // 0..2047 float4s
        const int r = idx >> 4;
        const int c = (idx & 15) << 2;
        float4 qv = *reinterpret_cast<const float4*>(&Qg[(size_t)r * DH_ + c]);
        unsigned* p = &Ps[r * PS_STRIDE + c];
        p[0] = f2tf(qv.x); p[1] = f2tf(qv.y); p[2] = f2tf(qv.z); p[3] = f2tf(qv.w);
    }
    __syncthreads();

    // Load Q fragments (8 k-steps over d=64)
    unsigned qf[8][4];
    #pragma unroll
    for (int kk = 0; kk < 8; kk++) {
        const int base = (wrp * 16 + g) * PS_STRIDE + kk * 8 + t;
        qf[kk][0] = Ps[base];
        qf[kk][1] = Ps[base + 8 * PS_STRIDE];
        qf[kk][2] = Ps[base + 4];
        qf[kk][3] = Ps[base + 8 * PS_STRIDE + 4];
    }

    float oacc[8][4];
    #pragma unroll
    for (int j = 0; j < 8; j++)
        #pragma unroll
        for (int r = 0; r < 4; r++) oacc[j][r] = 0.0f;
    float m0 = -INFINITY, m1 = -INFINITY, l0 = 0.0f, l1 = 0.0f;

    for (int kt = 0; kt < S_ / 64; kt++) {
        __syncthreads();   // prior iter's PV reads done (iter0: Q frag loads done)

        // Stage K, V tiles (64x64 each)
        #pragma unroll
        for (int it = 0; it < 4; it++) {
            const int idx = tid + it * 256;
            const int r = idx >> 4;
            const int c = (idx & 15) << 2;
            float4 kv = *reinterpret_cast<const float4*>(
                &Kg[(size_t)(kt * 64 + r) * DH_ + c]);
            unsigned* kp = &Ks[r * KS_STRIDE + c];
            kp[0] = f2tf(kv.x); kp[1] = f2tf(kv.y); kp[2] = f2tf(kv.z); kp[3] = f2tf(kv.w);
            float4 vv = *reinterpret_cast<const float4*>(
                &Vg[(size_t)(kt * 64 + r) * DH_ + c]);
            unsigned* vp = &Vs[r * VS_STRIDE + c];
            vp[0] = f2tf(vv.x); vp[1] = f2tf(vv.y); vp[2] = f2tf(vv.z); vp[3] = f2tf(vv.w);
        }
        __syncthreads();

        // S = Q @ K^T (warp: m16 x n64, k=64)
        float sacc[8][4];
        #pragma unroll
        for (int j = 0; j < 8; j++)
            #pragma unroll
            for (int r = 0; r < 4; r++) sacc[j][r] = 0.0f;

        #pragma unroll
        for (int kk = 0; kk < 8; kk++) {
            #pragma unroll
            for (int j = 0; j < 8; j++) {
                const int bbase = (j * 8 + g) * KS_STRIDE + kk * 8 + t;
                mma_tf32(sacc[j], qf[kk][0], qf[kk][1], qf[kk][2], qf[kk][3],
                         Ks[bbase], Ks[bbase + 4]);
            }
        }

        // scale + online softmax (rows g and g+8 of this warp's m16)
        const float scale = 0.125f;
        float mx0 = -INFINITY, mx1 = -INFINITY;
        #pragma unroll
        for (int j = 0; j < 8; j++) {
            sacc[j][0] *= scale; sacc[j][1] *= scale;
            sacc[j][2] *= scale; sacc[j][3] *= scale;
            mx0 = fmaxf(mx0, fmaxf(sacc[j][0], sacc[j][1]));
            mx1 = fmaxf(mx1, fmaxf(sacc[j][2], sacc[j][3]));
        }
        #pragma unroll
        for (int off = 1; off <= 2; off <<= 1) {
            mx0 = fmaxf(mx0, __shfl_xor_sync(0xffffffffu, mx0, off));
            mx1 = fmaxf(mx1, __shfl_xor_sync(0xffffffffu, mx1, off));
        }
        const float mn0 = fmaxf(m0, mx0);
        const float mn1 = fmaxf(m1, mx1);
        const float corr0 = __expf(m0 - mn0);
        const float corr1 = __expf(m1 - mn1);
        m0 = mn0; m1 = mn1;

        float sum0 = 0.0f, sum1 = 0.0f;
        #pragma unroll
        for (int j = 0; j < 8; j++) {
            sacc[j][0] = __expf(sacc[j][0] - mn0);
            sacc[j][1] = __expf(sacc[j][1] - mn0);
            sacc[j][2] = __expf(sacc[j][2] - mn1);
            sacc[j][3] = __expf(sacc[j][3] - mn1);
            sum0 += sacc[j][0] + sacc[j][1];
            sum1 += sacc[j][2] + sacc[j][3];
        }
        #pragma unroll
        for (int off = 1; off <= 2; off <<= 1) {
            sum0 += __shfl_xor_sync(0xffffffffu, sum0, off);
            sum1 += __shfl_xor_sync(0xffffffffu, sum1, off);
        }
        l0 = l0 * corr0 + sum0;
        l1 = l1 * corr1 + sum1;

        // rescale O
        #pragma unroll
        for (int j = 0; j < 8; j++) {
            oacc[j][0] *= corr0; oacc[j][1] *= corr0;
            oacc[j][2] *= corr1; oacc[j][3] *= corr1;
        }

        // store P (tf32) into Ps — only this warp's own rows; warp-local ordering
        #pragma unroll
        for (int j = 0; j < 8; j++) {
            const int base = (wrp * 16 + g) * PS_STRIDE + j * 8 + 2 * t;
            Ps[base]     = f2tf(sacc[j][0]);
            Ps[base + 1] = f2tf(sacc[j][1]);
            Ps[base + 8 * PS_STRIDE]     = f2tf(sacc[j][2]);
            Ps[base + 8 * PS_STRIDE + 1] = f2tf(sacc[j][3]);
        }
        __syncwarp();

        // O += P @ V  (k = 64 key positions, n = d 64)
        #pragma unroll
        for (int kk = 0; kk < 8; kk++) {
            const int abase = (wrp * 16 + g) * PS_STRIDE + kk * 8 + t;
            const unsigned a0 = Ps[abase];
            const unsigned a1 = Ps[abase + 8 * PS_STRIDE];
            const unsigned a2 = Ps[abase + 4];
            const unsigned a3 = Ps[abase + 8 * PS_STRIDE + 4];
            #pragma unroll
            for (int j = 0; j < 8; j++) {
                const int vb = (kk * 8 + t) * VS_STRIDE + j * 8 + g;
                mma_tf32(oacc[j], a0, a1, a2, a3, Vs[vb], Vs[vb + 4 * VS_STRIDE]);
            }
        }
    }

    // Final: normalize + store [B, S, D]
    const float inv0 = 1.0f / l0;
    const float inv1 = 1.0f / l1;
    const int row0 = qt * 128 + wrp * 16 + g;
    const int row1 = row0 + 8;
    const size_t o0 = ((size_t)(b * S_ + row0)) * D_ + h * DH_;
    const size_t o1 = ((size_t)(b * S_ + row1)) * D_ + h * DH_;
    #pragma unroll
    for (int j = 0; j < 8; j++) {
        const int d = j * 8 + 2 * t;
        *reinterpret_cast<float2*>(&out[o0 + d]) =
            make_float2(oacc[j][0] * inv0, oacc[j][1] * inv0);
        *reinterpret_cast<float2*>(&out[o1 + d]) =
            make_float2(oacc[j][2] * inv1, oacc[j][3] * inv1);
    }
}

// ---------------------------------------------------------------------------
extern "C" void kernel_launch(void* const* d_in, const int* in_sizes, int n_in,
                              void* d_out, int out_size)
{
    const float* x  = (const float*)d_in[0];
    const float* Wq = (const float*)d_in[1];
    const float* bq = (const float*)d_in[2];
    const float* Wk = (const float*)d_in[3];
    const float* bk = (const float*)d_in[4];
    const float* Wv = (const float*)d_in[5];
    const float* bv = (const float*)d_in[6];
    float* out = (float*)d_out;

    dim3 g1(D_ / 128, M_ / 128, 3);
    qkv_gemm_tc<<<g1, 256>>>(x, Wq, bq, Wk, bk, Wv, bv);

    const int smem_bytes = ATTN_SMEM_U32 * sizeof(unsigned);
    cudaFuncSetAttribute(attn_tc,
                         cudaFuncAttributeMaxDynamicSharedMemorySize, smem_bytes);
    dim3 g2(S_ / 128, H_, B_);
    attn_tc<<<g2, 256, smem_bytes>>>(out);
}